// round 16
// baseline (speedup 1.0000x reference)
#include <cuda_runtime.h>
#include <cuda_bf16.h>
#include <cstdint>

#define B_  2
#define S_  2048
#define D_  1024
#define H_  16
#define DK_ 64
#define NEGV -1.0e9f
#define NELEM (B_ * S_ * D_)
#define WELEM (D_ * D_)

// Scratch (allocation-free rule: __device__ globals) — all pre-split bf16 hi/lo
__device__ __nv_bfloat16 g_xh[3][NELEM];   // split inputs: query,key,value
__device__ __nv_bfloat16 g_xl[3][NELEM];
__device__ __nv_bfloat16 g_wh[4][WELEM];   // split weights: wq,wk,wv,wo
__device__ __nv_bfloat16 g_wl[4][WELEM];
__device__ __nv_bfloat16 g_ph[3][NELEM];   // projections: q(*0.125),k,v
__device__ __nv_bfloat16 g_pl[3][NELEM];
__device__ __nv_bfloat16 g_ch[NELEM];      // attention context (split)
__device__ __nv_bfloat16 g_cl[NELEM];

// ===========================================================================
// Helpers
// ===========================================================================
#define MMA16816(c, a, b) \
    asm volatile("mma.sync.aligned.m16n8k16.row.col.f32.bf16.bf16.f32 " \
        "{%0,%1,%2,%3}, {%4,%5,%6,%7}, {%8,%9}, {%0,%1,%2,%3};" \
        : "+f"((c)[0]), "+f"((c)[1]), "+f"((c)[2]), "+f"((c)[3]) \
        : "r"((a)[0]), "r"((a)[1]), "r"((a)[2]), "r"((a)[3]), \
          "r"((b)[0]), "r"((b)[1]))

#define LDSM_X4(d, addr) \
    asm volatile("ldmatrix.sync.aligned.m8n8.x4.shared.b16 {%0,%1,%2,%3}, [%4];" \
        : "=r"((d)[0]), "=r"((d)[1]), "=r"((d)[2]), "=r"((d)[3]) : "r"(addr))

#define LDSM_X4T(d, addr) \
    asm volatile("ldmatrix.sync.aligned.m8n8.x4.trans.shared.b16 {%0,%1,%2,%3}, [%4];" \
        : "=r"((d)[0]), "=r"((d)[1]), "=r"((d)[2]), "=r"((d)[3]) : "r"(addr))

#define CP16(dst, src) \
    asm volatile("cp.async.ca.shared.global [%0], [%1], 16;" \
        :: "r"(dst), "l"(src) : "memory")
#define CP_COMMIT() asm volatile("cp.async.commit_group;" ::: "memory")
#define CP_WAIT0()  asm volatile("cp.async.wait_group 0;" ::: "memory")

__device__ __forceinline__ uint32_t smem_u32(const void* p) {
    uint32_t a;
    asm("{ .reg .u64 t; cvta.to.shared.u64 t, %1; cvt.u32.u64 %0, t; }"
        : "=r"(a) : "l"(p));
    return a;
}

__device__ __forceinline__ void split4(float4 a, uint2& hi, uint2& lo) {
    __nv_bfloat162 h0 = __floats2bfloat162_rn(a.x, a.y);
    __nv_bfloat162 h1 = __floats2bfloat162_rn(a.z, a.w);
    float2 f0 = __bfloat1622float2(h0), f1 = __bfloat1622float2(h1);
    __nv_bfloat162 l0 = __floats2bfloat162_rn(a.x - f0.x, a.y - f0.y);
    __nv_bfloat162 l1 = __floats2bfloat162_rn(a.z - f1.x, a.w - f1.y);
    hi.x = *(uint32_t*)&h0; hi.y = *(uint32_t*)&h1;
    lo.x = *(uint32_t*)&l0; lo.y = *(uint32_t*)&l1;
}

// ===========================================================================
// Pre-split pass: fp32 -> (bf16 hi, bf16 lo) for q,k,v and 4 weights.
// ===========================================================================
__global__ __launch_bounds__(256) void presplit(
    const float* __restrict__ q, const float* __restrict__ k,
    const float* __restrict__ v,
    const float* __restrict__ wq, const float* __restrict__ wk,
    const float* __restrict__ wv, const float* __restrict__ wo)
{
    const int z = blockIdx.z;
    const float* src;
    __nv_bfloat16 *dh, *dl;
    int count;
    if (z < 3) {
        src = (z == 0) ? q : (z == 1) ? k : v;
        dh = g_xh[z]; dl = g_xl[z]; count = NELEM;
    } else {
        const int w = z - 3;
        src = (w == 0) ? wq : (w == 1) ? wk : (w == 2) ? wv : wo;
        dh = g_wh[w]; dl = g_wl[w]; count = WELEM;
    }
    const int base = (blockIdx.x * 256 + threadIdx.x) * 8;
    if (base >= count) return;
    float4 a = *(const float4*)(src + base);
    float4 b = *(const float4*)(src + base + 4);
    uint2 h0, l0, h1, l1;
    split4(a, h0, l0);
    split4(b, h1, l1);
    *(uint4*)(dh + base) = make_uint4(h0.x, h0.y, h1.x, h1.y);
    *(uint4*)(dl + base) = make_uint4(l0.x, l0.y, l1.x, l1.y);
}

// ===========================================================================
// GEMM mainloop: pure bf16, R14-style LDG-prefetch + double-buffered STS.
// CTA 128x128, warps 2(m) x 4(n), k-chunk 32.
// Row layout per tensor: [hi 64B | lo 64B | pad 16] stride 144.
// Per chunk: ks0 MMA -> LDG(ck+1) -> ks1 MMA -> STS(ck+1) -> sync.
// ===========================================================================
#define GFS 144
#define GB_OFF (128 * GFS)             // 18432
#define GSTAGE (2 * 128 * GFS)         // 36864
#define GEMM_SMEM (2 * GSTAGE)         // 73728

__device__ __forceinline__ void gemm_mainloop_bf(
    const __nv_bfloat16* __restrict__ AH, const __nv_bfloat16* __restrict__ AL,
    const __nv_bfloat16* __restrict__ BH, const __nv_bfloat16* __restrict__ BL,
    int K, char* smc, int m0, int n0, float acc[4][4][4])
{
    const uint32_t sb = smem_u32(smc);
    const int tid = threadIdx.x;
    const int wid = tid >> 5, lane = tid & 31;
    const int warp_m = wid & 1, warp_n = wid >> 1;
    const int l7 = lane & 7;
    const uint32_t aRel =
        (uint32_t)(warp_m * 64 + l7 + ((lane >> 3) & 1) * 8) * GFS +
        (uint32_t)(lane >> 4) * 16;
    const uint32_t bRel =
        (uint32_t)(warp_n * 32 + l7 + ((lane >> 4) & 1) * 8) * GFS +
        (uint32_t)((lane >> 3) & 1) * 16;

    // Staging: thread (r, hf) moves 64B of row r (hi or lo image) for A and B.
    const int r = tid >> 1, hf = tid & 1;
    const __nv_bfloat16* srcA = (hf ? AL : AH) + (size_t)(m0 + r) * K;
    const __nv_bfloat16* srcB = (hf ? BL : BH) + (size_t)(n0 + r) * K;
    const uint32_t soff = (uint32_t)r * GFS + hf * 64;

#pragma unroll
    for (int mi = 0; mi < 4; mi++)
#pragma unroll
        for (int ni = 0; ni < 4; ni++)
#pragma unroll
            for (int c = 0; c < 4; c++) acc[mi][ni][c] = 0.f;

    const int nchunks = K / 32;

    // Prologue: stage chunk 0 into buf 0 directly.
    {
        const uint4* a0 = (const uint4*)srcA;
        const uint4* b0 = (const uint4*)srcB;
#pragma unroll
        for (int j = 0; j < 4; j++) {
            *(uint4*)(smc + soff + j * 16) = a0[j];
            *(uint4*)(smc + GB_OFF + soff + j * 16) = b0[j];
        }
    }
    __syncthreads();

    for (int ck = 0; ck < nchunks; ck++) {
        const uint32_t bb = sb + (uint32_t)(ck & 1) * GSTAGE;
        uint4 pA[4], pB[4];

        // ---- ks = 0 ----
        {
            uint32_t bh[2][4], bl[2][4];
#pragma unroll
            for (int np = 0; np < 2; np++) {
                LDSM_X4(bh[np], bb + GB_OFF + bRel + np * (16 * GFS));
                LDSM_X4(bl[np], bb + GB_OFF + bRel + np * (16 * GFS) + 64);
            }
#pragma unroll
            for (int mi = 0; mi < 4; mi++) {
                uint32_t ah[4], al[4];
                LDSM_X4(ah, bb + aRel + mi * (16 * GFS));
                LDSM_X4(al, bb + aRel + mi * (16 * GFS) + 64);
#pragma unroll
                for (int ni = 0; ni < 4; ni++) {
                    uint32_t* bhf = &bh[ni >> 1][(ni & 1) * 2];
                    uint32_t* blf = &bl[ni >> 1][(ni & 1) * 2];
                    MMA16816(acc[mi][ni], ah, bhf);
                    MMA16816(acc[mi][ni], ah, blf);
                    MMA16816(acc[mi][ni], al, bhf);
                }
            }
        }

        // LDG of next chunk (latency covered by ks=1 MMA phase).
        if (ck + 1 < nchunks) {
            const uint4* pa = (const uint4*)(srcA + (ck + 1) * 32);
            const uint4* pb = (const uint4*)(srcB + (ck + 1) * 32);
#pragma unroll
            for (int j = 0; j < 4; j++) { pA[j] = pa[j]; pB[j] = pb[j]; }
        }

        // ---- ks = 1 ----
        {
            uint32_t bh[2][4], bl[2][4];
#pragma unroll
            for (int np = 0; np < 2; np++) {
                LDSM_X4(bh[np], bb + GB_OFF + bRel + np * (16 * GFS) + 32);
                LDSM_X4(bl[np], bb + GB_OFF + bRel + np * (16 * GFS) + 96);
            }
#pragma unroll
            for (int mi = 0; mi < 4; mi++) {
                uint32_t ah[4], al[4];
                LDSM_X4(ah, bb + aRel + mi * (16 * GFS) + 32);
                LDSM_X4(al, bb + aRel + mi * (16 * GFS) + 96);
#pragma unroll
                for (int ni = 0; ni < 4; ni++) {
                    uint32_t* bhf = &bh[ni >> 1][(ni & 1) * 2];
                    uint32_t* blf = &bl[ni >> 1][(ni & 1) * 2];
                    MMA16816(acc[mi][ni], ah, bhf);
                    MMA16816(acc[mi][ni], ah, blf);
                    MMA16816(acc[mi][ni], al, bhf);
                }
            }
        }

        // Stage next chunk into the other buffer.
        if (ck + 1 < nchunks) {
            char* ob = smc + ((ck + 1) & 1) * GSTAGE;
#pragma unroll
            for (int j = 0; j < 4; j++) {
                *(uint4*)(ob + soff + j * 16) = pA[j];
                *(uint4*)(ob + GB_OFF + soff + j * 16) = pB[j];
            }
        }
        __syncthreads();
    }
}

// NOTE on ks offsets: hi bytes [0,64) hold k0..31 of the chunk; x4 column
// halves select k via (lane>>4)*16 in aRel / ((lane>>3)&1)*16 in bRel, and
// ks=1 adds +32 bytes (k16..31). lo image mirrors at +64.

// ---- QKV projections: split bf16 epilogue (q scaled by 0.125) ----
__global__ __launch_bounds__(256, 2) void gemm_split(
    const float* __restrict__ bs0, const float* __restrict__ bs1,
    const float* __restrict__ bs2)
{
    extern __shared__ char smc[];
    const int z = blockIdx.z;
    const float* bias = (z == 0) ? bs0 : (z == 1) ? bs1 : bs2;
    const float scale = (z == 0) ? 0.125f : 1.0f;
    const int m0 = blockIdx.y * 128, n0 = blockIdx.x * 128;

    float acc[4][4][4];
    gemm_mainloop_bf(g_xh[z], g_xl[z], g_wh[z], g_wl[z], D_, smc, m0, n0, acc);

    __nv_bfloat16* Ch = g_ph[z];
    __nv_bfloat16* Cl = g_pl[z];
    const int wid = threadIdx.x >> 5, lane = threadIdx.x & 31;
    const int g = lane >> 2, t = lane & 3;
    const int warp_m = wid & 1, warp_n = wid >> 1;

#pragma unroll
    for (int mi = 0; mi < 4; mi++) {
        const int row0 = m0 + warp_m * 64 + mi * 16 + g;
#pragma unroll
        for (int ni = 0; ni < 4; ni++) {
            const int col = n0 + warp_n * 32 + ni * 8 + t * 2;
            float2 bi = *(const float2*)&bias[col];
            float c0 = (acc[mi][ni][0] + bi.x) * scale;
            float c1 = (acc[mi][ni][1] + bi.y) * scale;
            float c2 = (acc[mi][ni][2] + bi.x) * scale;
            float c3 = (acc[mi][ni][3] + bi.y) * scale;
            __nv_bfloat162 h01 = __floats2bfloat162_rn(c0, c1);
            __nv_bfloat162 h23 = __floats2bfloat162_rn(c2, c3);
            float2 f01 = __bfloat1622float2(h01);
            float2 f23 = __bfloat1622float2(h23);
            __nv_bfloat162 l01 = __floats2bfloat162_rn(c0 - f01.x, c1 - f01.y);
            __nv_bfloat162 l23 = __floats2bfloat162_rn(c2 - f23.x, c3 - f23.y);
            *(__nv_bfloat162*)&Ch[(size_t)row0 * D_ + col] = h01;
            *(__nv_bfloat162*)&Ch[(size_t)(row0 + 8) * D_ + col] = h23;
            *(__nv_bfloat162*)&Cl[(size_t)row0 * D_ + col] = l01;
            *(__nv_bfloat162*)&Cl[(size_t)(row0 + 8) * D_ + col] = l23;
        }
    }
}

// ---- Output projection: fp32 epilogue ----
__global__ __launch_bounds__(256, 2) void gemm_f32(
    const float* __restrict__ bias, float* __restrict__ C)
{
    extern __shared__ char smc[];
    const int m0 = blockIdx.y * 128, n0 = blockIdx.x * 128;

    float acc[4][4][4];
    gemm_mainloop_bf(g_ch, g_cl, g_wh[3], g_wl[3], D_, smc, m0, n0, acc);

    const int wid = threadIdx.x >> 5, lane = threadIdx.x & 31;
    const int g = lane >> 2, t = lane & 3;
    const int warp_m = wid & 1, warp_n = wid >> 1;

#pragma unroll
    for (int mi = 0; mi < 4; mi++) {
        const int row0 = m0 + warp_m * 64 + mi * 16 + g;
#pragma unroll
        for (int ni = 0; ni < 4; ni++) {
            const int col = n0 + warp_n * 32 + ni * 8 + t * 2;
            float2 bi = *(const float2*)&bias[col];
            float2 o0, o1;
            o0.x = acc[mi][ni][0] + bi.x;
            o0.y = acc[mi][ni][1] + bi.y;
            o1.x = acc[mi][ni][2] + bi.x;
            o1.y = acc[mi][ni][3] + bi.y;
            *(float2*)&C[(size_t)row0 * D_ + col] = o0;
            *(float2*)&C[(size_t)(row0 + 8) * D_ + col] = o1;
        }
    }
}

// ===========================================================================
// Tensor-core flash attention (unchanged from R15; cp.async double-buffered,
// x4 K frags, x4.trans V frags, split-bf16 ctx epilogue).
// ===========================================================================
#define FSTB 144
#define FQ_H 0
#define FQ_L (128 * FSTB)              // 18432
#define FB_KH 0
#define FB_KL (64 * FSTB)              // 9216
#define FB_VH (2 * 64 * FSTB)          // 18432
#define FB_VL (3 * 64 * FSTB)          // 27648
#define FBUF_SZ (4 * 64 * FSTB)        // 36864
#define FBUF0 (2 * 128 * FSTB)         // 36864
#define FLASH_SMEM (FBUF0 + 2 * FBUF_SZ)   // 110592

__global__ __launch_bounds__(256, 2) void flash_tc(const int* __restrict__ mask)
{
    extern __shared__ char smf[];
    const uint32_t sb = smem_u32(smf);
    const int tid = threadIdx.x;
    const int wid = tid >> 5, lane = tid & 31;
    const int g = lane >> 2, t = lane & 3;
    const int b = blockIdx.z, h = blockIdx.y;
    const int q0 = blockIdx.x * 128;

    const __nv_bfloat16* QH = g_ph[0];
    const __nv_bfloat16* QL = g_pl[0];
    const __nv_bfloat16* KH = g_ph[1];
    const __nv_bfloat16* KL = g_pl[1];
    const __nv_bfloat16* VH = g_ph[2];
    const __nv_bfloat16* VL = g_pl[2];

    const size_t bS = (size_t)b * S_;
    const int* Mb = mask + bS * S_;

    const int l7 = lane & 7;
    const uint32_t qBase = sb +
        (uint32_t)(wid * 16 + l7 + ((lane >> 3) & 1) * 8) * FSTB +
        (uint32_t)(lane >> 4) * 16;
    const uint32_t k4Rel =
        (uint32_t)(l7 + ((lane >> 4) & 1) * 8) * FSTB +
        (uint32_t)((lane >> 3) & 1) * 16;
    const uint32_t v4Rel =
        (uint32_t)(l7 + ((lane >> 3) & 1) * 8) * FSTB +
        (uint32_t)((lane >> 4) & 1) * 16;

    const int kr = tid >> 2;
    const uint32_t cc = (uint32_t)(tid & 3) * 32;
    const size_t kvElemBase = (bS + kr) * D_ + h * DK_;

    // ---- Prologue: cp.async Q (whole) + K/V tile 0 ----
    {
        const int qr = tid >> 1;
        const uint32_t qcc = (uint32_t)(tid & 1) * 64;
        const char* srcQH = (const char*)(QH + (bS + q0 + qr) * D_ + h * DK_) + qcc;
        const char* srcQL = (const char*)(QL + (bS + q0 + qr) * D_ + h * DK_) + qcc;
        const uint32_t dq = sb + (uint32_t)qr * FSTB + qcc;
#pragma unroll
        for (int j = 0; j < 4; j++) {
            CP16(dq + FQ_H + j * 16, srcQH + j * 16);
            CP16(dq + FQ_L + j * 16, srcQL + j * 16);
        }
        const uint32_t d0 = sb + FBUF0 + (uint32_t)kr * FSTB + cc;
        const char* sKH = (const char*)(KH + kvElemBase) + cc;
        const char* sKL = (const char*)(KL + kvElemBase) + cc;
        const char* sVH = (const char*)(VH + kvElemBase) + cc;
        const char* sVL = (const char*)(VL + kvElemBase) + cc;
        CP16(d0 + FB_KH, sKH);       CP16(d0 + FB_KH + 16, sKH + 16);
        CP16(d0 + FB_KL, sKL);       CP16(d0 + FB_KL + 16, sKL + 16);
        CP16(d0 + FB_VH, sVH);       CP16(d0 + FB_VH + 16, sVH + 16);
        CP16(d0 + FB_VL, sVL);       CP16(d0 + FB_VL + 16, sVL + 16);
        CP_COMMIT();
        CP_WAIT0();
    }
    __syncthreads();

    // ---- Hoist Q hi+lo fragments for the whole kernel ----
    uint32_t qh[4][4], ql[4][4];
#pragma unroll
    for (int ks = 0; ks < 4; ks++) {
        LDSM_X4(qh[ks], qBase + FQ_H + ks * 32);
        LDSM_X4(ql[ks], qBase + FQ_L + ks * 32);
    }

    float O[8][4];
#pragma unroll
    for (int ni = 0; ni < 8; ni++)
#pragma unroll
        for (int c = 0; c < 4; c++) O[ni][c] = 0.f;

    float m0r = -3.0e38f, m1r = -3.0e38f;
    float l0r = 0.f, l1r = 0.f;

    const int r0g = q0 + wid * 16 + g;
    const int r1g = r0g + 8;

    const int NT = S_ / 64;
    for (int it = 0; it < NT; it++) {
        const uint32_t bb = sb + FBUF0 + (uint32_t)(it & 1) * FBUF_SZ;
        const int kt = it * 64;

        // ---- S = Qs @ K^T (3-term split, x4-paired K frags) ----
        float s[8][4];
#pragma unroll
        for (int ni = 0; ni < 8; ni++)
#pragma unroll
            for (int c = 0; c < 4; c++) s[ni][c] = 0.f;

#pragma unroll
        for (int ks = 0; ks < 4; ks++) {
#pragma unroll
            for (int np = 0; np < 4; np++) {
                uint32_t kh4[4], kl4[4];
                LDSM_X4(kh4, bb + FB_KH + k4Rel + np * (16 * FSTB) + ks * 32);
                LDSM_X4(kl4, bb + FB_KL + k4Rel + np * (16 * FSTB) + ks * 32);
                MMA16816(s[2 * np], qh[ks], kh4);
                MMA16816(s[2 * np], qh[ks], kl4);
                MMA16816(s[2 * np], ql[ks], kh4);
                MMA16816(s[2 * np + 1], qh[ks], kh4 + 2);
                MMA16816(s[2 * np + 1], qh[ks], kl4 + 2);
                MMA16816(s[2 * np + 1], ql[ks], kh4 + 2);
            }
        }

        // ---- Mask ----
#pragma unroll
        for (int ni = 0; ni < 8; ni++) {
            const int c = kt + ni * 8 + t * 2;
            int2 mk0 = *(const int2*)(Mb + (size_t)r0g * S_ + c);
            int2 mk1 = *(const int2*)(Mb + (size_t)r1g * S_ + c);
            if (!mk0.x) s[ni][0] = NEGV;
            if (!mk0.y) s[ni][1] = NEGV;
            if (!mk1.x) s[ni][2] = NEGV;
            if (!mk1.y) s[ni][3] = NEGV;
        }

        // ---- Online softmax (within t-quad) ----
        float mx0 = s[0][0], mx1 = s[0][2];
#pragma unroll
        for (int ni = 0; ni < 8; ni++) {
            mx0 = fmaxf(mx0, fmaxf(s[ni][0], s[ni][1]));
            mx1 = fmaxf(mx1, fmaxf(s[ni][2], s[ni][3]));
        }
        mx0 = fmaxf(mx0, __shfl_xor_sync(0xffffffffu, mx0, 1));
        mx0 = fmaxf(mx0, __shfl_xor_sync(0xffffffffu, mx0, 2));
        mx1 = fmaxf(mx1, __shfl_xor_sync(0xffffffffu, mx1, 1));
        mx1 = fmaxf(mx1, __shfl_xor_sync(0xffffffffu, mx1, 2));

        const float mn0 = fmaxf(m0r, mx0);
        const float mn1 = fmaxf(m1r, mx1);
        const float a0 = __expf(m0r - mn0);
        const float a1 = __expf(m1r - mn1);
        m0r = mn0; m1r = mn1;

        float sum0 = 0.f, sum1 = 0.f;
#pragma unroll
        for (int ni = 0; ni < 8; ni++) {
            s[ni][0] = __expf(s[ni][0] - mn0);
            s[ni][1] = __expf(s[ni][1] - mn0);
            s[ni][2] = __expf(s[ni][2] - mn1);
            s[ni][3] = __expf(s[ni][3] - mn1);
            sum0 += s[ni][0] + s[ni][1];
            sum1 += s[ni][2] + s[ni][3];
        }
        sum0 += __shfl_xor_sync(0xffffffffu, sum0, 1);
        sum0 += __shfl_xor_sync(0xffffffffu, sum0, 2);
        sum1 += __shfl_xor_sync(0xffffffffu, sum1, 1);
        sum1 += __shfl_xor_sync(0xffffffffu, sum1, 2);
        l0r = l0r * a0 + sum0;
        l1r = l1r * a1 + sum1;

#pragma unroll
        for (int ni = 0; ni < 8; ni++) {
            O[ni][0] *= a0; O[ni][1] *= a0;
            O[ni][2] *= a1; O[ni][3] *= a1;
        }

        // ---- cp.async next tile ----
        if (it + 1 < NT) {
            const size_t nb = kvElemBase + (size_t)(kt + 64) * D_;
            const uint32_t dn = sb + FBUF0 + (uint32_t)((it + 1) & 1) * FBUF_SZ
                              + (uint32_t)kr * FSTB + cc;
            const char* sKH = (const char*)(KH + nb) + cc;
            const char* sKL = (const char*)(KL + nb) + cc;
            const char* sVH = (const char*)(VH + nb) + cc;
            const char* sVL = (const char*)(VL + nb) + cc;
            CP16(dn + FB_KH, sKH);    CP16(dn + FB_KH + 16, sKH + 16);
            CP16(dn + FB_KL, sKL);    CP16(dn + FB_KL + 16, sKL + 16);
            CP16(dn + FB_VH, sVH);    CP16(dn + FB_VH + 16, sVH + 16);
            CP16(dn + FB_VL, sVL);    CP16(dn + FB_VL + 16, sVL + 16);
            CP_COMMIT();
        }

        // ---- PV: O += P @ V (x4.trans-paired V frags) ----
#pragma unroll
        for (int ksp = 0; ksp < 4; ksp++) {
            uint32_t pah[4], pal[4];
#pragma unroll
            for (int hf = 0; hf < 2; hf++) {
                const float* p = s[2 * ksp + hf];
                __nv_bfloat162 h01 = __floats2bfloat162_rn(p[0], p[1]);
                __nv_bfloat162 h23 = __floats2bfloat162_rn(p[2], p[3]);
                float2 f01 = __bfloat1622float2(h01);
                float2 f23 = __bfloat1622float2(h23);
                __nv_bfloat162 l01 =
                    __floats2bfloat162_rn(p[0] - f01.x, p[1] - f01.y);
                __nv_bfloat162 l23 =
                    __floats2bfloat162_rn(p[2] - f23.x, p[3] - f23.y);
                pah[hf * 2 + 0] = *(const uint32_t*)&h01;
                pah[hf * 2 + 1] = *(const uint32_t*)&h23;
                pal[hf * 2 + 0] = *(const uint32_t*)&l01;
                pal[hf * 2 + 1] = *(const uint32_t*)&l23;
            }
#pragma unroll
            for (int np = 0; np < 4; np++) {
                uint32_t vh4[4], vl4[4];
                LDSM_X4T(vh4, bb + FB_VH + v4Rel + ksp * (16 * FSTB) + np * 32);
                LDSM_X4T(vl4, bb + FB_VL + v4Rel + ksp * (16 * FSTB) + np * 32);
                MMA16816(O[2 * np], pah, vh4);
                MMA16816(O[2 * np], pah, vl4);
                MMA16816(O[2 * np], pal, vh4);
                MMA16816(O[2 * np + 1], pah, vh4 + 2);
                MMA16816(O[2 * np + 1], pah, vl4 + 2);
                MMA16816(O[2 * np + 1], pal, vh4 + 2);
            }
        }

        CP_WAIT0();
        __syncthreads();
    }

    // ---- Final normalize + split-bf16 store of ctx ----
    const float ri0 = 1.f / l0r;
    const float ri1 = 1.f / l1r;
    __nv_bfloat16* C0h = g_ch + (bS + r0g) * D_ + h * DK_;
    __nv_bfloat16* C0l = g_cl + (bS + r0g) * D_ + h * DK_;
    __nv_bfloat16* C1h = g_ch + (bS + r1g) * D_ + h * DK_;
    __nv_bfloat16* C1l = g_cl + (bS + r1g) * D_ + h * DK_;
#pragma unroll
    for (int ni = 0; ni < 8; ni++) {
        const int c = ni * 8 + t * 2;
        float o0x = O[ni][0] * ri0, o0y = O[ni][1] * ri0;
        float o1x = O[ni][2] * ri1, o1y = O[ni][3] * ri1;
        __nv_bfloat162 h0 = __floats2bfloat162_rn(o0x, o0y);
        __nv_bfloat162 h1 = __floats2bfloat162_rn(o1x, o1y);
        float2 f0 = __bfloat1622float2(h0);
        float2 f1 = __bfloat1622float2(h1);
        __nv_bfloat162 l0 = __floats2bfloat162_rn(o0x - f0.x, o0y - f0.y);
        __nv_bfloat162 l1 = __floats2bfloat162_rn(o1x - f1.x, o1y - f1.y);
        *(__nv_bfloat162*)(C0h + c) = h0;
        *(__nv_bfloat162*)(C0l + c) = l0;
        *(__nv_bfloat162*)(C1h + c) = h1;
        *(__nv_bfloat162*)(C1l + c) = l1;
    }
}

// ---------------------------------------------------------------------------
// Launch
// ---------------------------------------------------------------------------
extern "C" void kernel_launch(void* const* d_in, const int* in_sizes, int n_in,
                              void* d_out, int out_size)
{
    const float* query = (const float*)d_in[0];
    const float* key   = (const float*)d_in[1];
    const float* value = (const float*)d_in[2];
    const int*   mask  = (const int*)d_in[3];
    const float* w_q = (const float*)d_in[4];
    const float* b_q = (const float*)d_in[5];
    const float* w_k = (const float*)d_in[6];
    const float* b_k = (const float*)d_in[7];
    const float* w_v = (const float*)d_in[8];
    const float* b_v = (const float*)d_in[9];
    const float* w_o = (const float*)d_in[10];
    const float* b_o = (const float*)d_in[11];

    cudaFuncSetAttribute(gemm_split,
                         cudaFuncAttributeMaxDynamicSharedMemorySize,
                         GEMM_SMEM);
    cudaFuncSetAttribute(gemm_f32,
                         cudaFuncAttributeMaxDynamicSharedMemorySize,
                         GEMM_SMEM);
    cudaFuncSetAttribute(flash_tc,
                         cudaFuncAttributeMaxDynamicSharedMemorySize,
                         FLASH_SMEM);

    // 1. Pre-split inputs + weights to bf16 hi/lo
    dim3 gpre(NELEM / (256 * 8), 1, 7);           // (2048, 1, 7)
    presplit<<<gpre, 256>>>(query, key, value, w_q, w_k, w_v, w_o);

    // 2. Fused QKV projections
    const int M = B_ * S_;
    dim3 gqkv(D_ / 128, M / 128, 3);              // 768 CTAs
    gemm_split<<<gqkv, 256, GEMM_SMEM>>>(b_q, b_k, b_v);

    // 3. Flash attention
    dim3 gflash(S_ / 128, H_, B_);                // 512 CTAs
    flash_tc<<<gflash, 256, FLASH_SMEM>>>(mask);

    // 4. Output projection
    dim3 gproj(D_ / 128, M / 128);
    gemm_f32<<<gproj, 256, GEMM_SMEM>>>(b_o, (float*)d_out);
}

// round 17
// speedup vs baseline: 1.8722x; 1.8722x over previous
#include <cuda_runtime.h>
#include <cuda_bf16.h>
#include <cstdint>

#define B_  2
#define S_  2048
#define D_  1024
#define H_  16
#define DK_ 64
#define NEGV -1.0e9f

// Scratch (allocation-free rule: __device__ globals)
// Pre-split bf16 hi/lo images of q(*0.125), k, v written by projection epilogue.
__device__ __nv_bfloat16 g_qh[B_ * S_ * D_];
__device__ __nv_bfloat16 g_ql[B_ * S_ * D_];
__device__ __nv_bfloat16 g_kh[B_ * S_ * D_];
__device__ __nv_bfloat16 g_kl[B_ * S_ * D_];
__device__ __nv_bfloat16 g_vh[B_ * S_ * D_];
__device__ __nv_bfloat16 g_vl[B_ * S_ * D_];
__device__ float g_ctx[B_ * S_ * D_];
__device__ uint32_t g_mb[B_ * S_ * (S_ / 32)];   // packed mask bits (2M words)

// ===========================================================================
// Common helpers
// ===========================================================================
#define MMA16816(c, a, b) \
    asm volatile("mma.sync.aligned.m16n8k16.row.col.f32.bf16.bf16.f32 " \
        "{%0,%1,%2,%3}, {%4,%5,%6,%7}, {%8,%9}, {%0,%1,%2,%3};" \
        : "+f"((c)[0]), "+f"((c)[1]), "+f"((c)[2]), "+f"((c)[3]) \
        : "r"((a)[0]), "r"((a)[1]), "r"((a)[2]), "r"((a)[3]), \
          "r"((b)[0]), "r"((b)[1]))

#define LDSM_X4(d, addr) \
    asm volatile("ldmatrix.sync.aligned.m8n8.x4.shared.b16 {%0,%1,%2,%3}, [%4];" \
        : "=r"((d)[0]), "=r"((d)[1]), "=r"((d)[2]), "=r"((d)[3]) : "r"(addr))

#define LDSM_X2(d, addr) \
    asm volatile("ldmatrix.sync.aligned.m8n8.x2.shared.b16 {%0,%1}, [%2];" \
        : "=r"((d)[0]), "=r"((d)[1]) : "r"(addr))

#define LDSM_X2T(d, addr) \
    asm volatile("ldmatrix.sync.aligned.m8n8.x2.trans.shared.b16 {%0,%1}, [%2];" \
        : "=r"((d)[0]), "=r"((d)[1]) : "r"(addr))

#define CP16(dst, src) \
    asm volatile("cp.async.ca.shared.global [%0], [%1], 16;" \
        :: "r"(dst), "l"(src) : "memory")
#define CP_COMMIT() asm volatile("cp.async.commit_group;" ::: "memory")
#define CP_WAIT0()  asm volatile("cp.async.wait_group 0;" ::: "memory")

__device__ __forceinline__ uint32_t smem_u32(const void* p) {
    uint32_t a;
    asm("{ .reg .u64 t; cvta.to.shared.u64 t, %1; cvt.u32.u64 %0, t; }"
        : "=r"(a) : "l"(p));
    return a;
}

// Convert 16 fp32 (4 float4) -> 16 bf16 hi + 16 bf16 lo via cvt.rn.bf16x2.
__device__ __forceinline__ void store_split16(
    const float4* v, char* hi, char* lo, uint32_t boff)
{
    uint32_t hw[8], lw[8];
#pragma unroll
    for (int q = 0; q < 4; q++) {
        __nv_bfloat162 h0 = __floats2bfloat162_rn(v[q].x, v[q].y);
        __nv_bfloat162 h1 = __floats2bfloat162_rn(v[q].z, v[q].w);
        float2 f0 = __bfloat1622float2(h0);
        float2 f1 = __bfloat1622float2(h1);
        __nv_bfloat162 l0 = __floats2bfloat162_rn(v[q].x - f0.x, v[q].y - f0.y);
        __nv_bfloat162 l1 = __floats2bfloat162_rn(v[q].z - f1.x, v[q].w - f1.y);
        hw[q * 2]     = *(const uint32_t*)&h0;
        hw[q * 2 + 1] = *(const uint32_t*)&h1;
        lw[q * 2]     = *(const uint32_t*)&l0;
        lw[q * 2 + 1] = *(const uint32_t*)&l1;
    }
    *(uint4*)(hi + boff)      = make_uint4(hw[0], hw[1], hw[2], hw[3]);
    *(uint4*)(hi + boff + 16) = make_uint4(hw[4], hw[5], hw[6], hw[7]);
    *(uint4*)(lo + boff)      = make_uint4(lw[0], lw[1], lw[2], lw[3]);
    *(uint4*)(lo + boff + 16) = make_uint4(lw[4], lw[5], lw[6], lw[7]);
}

// ===========================================================================
// Mask bitpack: int32[B,S,S] -> bits[B,S,S/32]  (nonzero -> 1)
// ===========================================================================
__global__ __launch_bounds__(256) void maskpack(const int* __restrict__ mask)
{
    const size_t i = (size_t)blockIdx.x * 256 + threadIdx.x;
    const int v = mask[i];
    const uint32_t bits = __ballot_sync(0xffffffffu, v != 0);
    if ((threadIdx.x & 31) == 0) g_mb[i >> 5] = bits;
}

// ===========================================================================
// GEMM mainloop (R14 verbatim): fp32 LDG + in-loop split, double-buffered,
// CTA 128x128, warps 2(m) x 4(n), B-frags hoisted across mi.
// ===========================================================================
#define GSTRIDE 80
#define GB_AH 0
#define GB_AL (128 * GSTRIDE)
#define GB_BH (2 * 128 * GSTRIDE)
#define GB_BL (3 * 128 * GSTRIDE)
#define GBUF_SZ (4 * 128 * GSTRIDE)     // 40960
#define GEMM_SMEM (2 * GBUF_SZ)         // 81920

__device__ __forceinline__ void gemm_mainloop(
    const float* __restrict__ A, const float* __restrict__ Bw,
    int K, char* smc, int m0, int n0, float acc[4][4][4])
{
    const uint32_t sb = smem_u32(smc);
    const int tid = threadIdx.x;
    const int wid = tid >> 5, lane = tid & 31;
    const int warp_m = wid & 1, warp_n = wid >> 1;
    const int l7 = lane & 7;
    const uint32_t aRel =
        (uint32_t)(warp_m * 64 + l7 + ((lane >> 3) & 1) * 8) * GSTRIDE +
        (uint32_t)(lane >> 4) * 16;
    const uint32_t bRel =
        (uint32_t)(warp_n * 32 + l7) * GSTRIDE +
        (uint32_t)((lane >> 3) & 1) * 16;

    const int r = tid >> 1, h = tid & 1;
    const float* gA = A + (size_t)(m0 + r) * K + h * 16;
    const float* gB = Bw + (size_t)(n0 + r) * K + h * 16;
    const uint32_t boff = (uint32_t)r * GSTRIDE + h * 32;

#pragma unroll
    for (int mi = 0; mi < 4; mi++)
#pragma unroll
        for (int ni = 0; ni < 4; ni++)
#pragma unroll
            for (int c = 0; c < 4; c++) acc[mi][ni][c] = 0.f;

    const int nchunks = K / 32;

    // Prologue: stage chunk 0 into buf0.
    {
        float4 vA[4], vB[4];
#pragma unroll
        for (int q = 0; q < 4; q++) {
            vA[q] = *(const float4*)(gA + q * 4);
            vB[q] = *(const float4*)(gB + q * 4);
        }
        store_split16(vA, smc + GB_AH, smc + GB_AL, boff);
        store_split16(vB, smc + GB_BH, smc + GB_BL, boff);
    }
    __syncthreads();

    for (int ck = 0; ck < nchunks; ck++) {
        const uint32_t bb = sb + (uint32_t)(ck & 1) * GBUF_SZ;
        float4 vA[4], vB[4];

        // ---- ks = 0 ----
        {
            uint32_t bh[4][2], bl[4][2];
#pragma unroll
            for (int ni = 0; ni < 4; ni++) {
                LDSM_X2(bh[ni], bb + GB_BH + bRel + ni * (8 * GSTRIDE));
                LDSM_X2(bl[ni], bb + GB_BL + bRel + ni * (8 * GSTRIDE));
            }
#pragma unroll
            for (int mi = 0; mi < 4; mi++) {
                uint32_t ah[4], al[4];
                LDSM_X4(ah, bb + GB_AH + aRel + mi * (16 * GSTRIDE));
                LDSM_X4(al, bb + GB_AL + aRel + mi * (16 * GSTRIDE));
#pragma unroll
                for (int ni = 0; ni < 4; ni++) {
                    MMA16816(acc[mi][ni], ah, bh[ni]);
                    MMA16816(acc[mi][ni], ah, bl[ni]);
                    MMA16816(acc[mi][ni], al, bh[ni]);
                }
            }
        }

        // LDG of next chunk, latency covered by ks=1 MMA phase.
        if (ck + 1 < nchunks) {
            const float* pa = gA + (ck + 1) * 32;
            const float* pb = gB + (ck + 1) * 32;
#pragma unroll
            for (int q = 0; q < 4; q++) {
                vA[q] = *(const float4*)(pa + q * 4);
                vB[q] = *(const float4*)(pb + q * 4);
            }
        }

        // ---- ks = 1 ----
        {
            uint32_t bh[4][2], bl[4][2];
#pragma unroll
            for (int ni = 0; ni < 4; ni++) {
                LDSM_X2(bh[ni], bb + GB_BH + bRel + ni * (8 * GSTRIDE) + 32);
                LDSM_X2(bl[ni], bb + GB_BL + bRel + ni * (8 * GSTRIDE) + 32);
            }
#pragma unroll
            for (int mi = 0; mi < 4; mi++) {
                uint32_t ah[4], al[4];
                LDSM_X4(ah, bb + GB_AH + aRel + mi * (16 * GSTRIDE) + 32);
                LDSM_X4(al, bb + GB_AL + aRel + mi * (16 * GSTRIDE) + 32);
#pragma unroll
                for (int ni = 0; ni < 4; ni++) {
                    MMA16816(acc[mi][ni], ah, bh[ni]);
                    MMA16816(acc[mi][ni], ah, bl[ni]);
                    MMA16816(acc[mi][ni], al, bh[ni]);
                }
            }
        }

        // Stage next chunk into the other buffer.
        if (ck + 1 < nchunks) {
            char* ob = smc + ((ck + 1) & 1) * GBUF_SZ;
            store_split16(vA, ob + GB_AH, ob + GB_AL, boff);
            store_split16(vB, ob + GB_BH, ob + GB_BL, boff);
        }
        __syncthreads();
    }
}

// ---- QKV projection: epilogue writes pre-split bf16 hi/lo (+scale) ----
__global__ __launch_bounds__(256, 2) void gemm_split(
    const float* __restrict__ A0, const float* __restrict__ A1,
    const float* __restrict__ A2,
    const float* __restrict__ W0, const float* __restrict__ W1,
    const float* __restrict__ W2,
    const float* __restrict__ bs0, const float* __restrict__ bs1,
    const float* __restrict__ bs2,
    __nv_bfloat16* __restrict__ H0, __nv_bfloat16* __restrict__ H1,
    __nv_bfloat16* __restrict__ H2,
    __nv_bfloat16* __restrict__ L0, __nv_bfloat16* __restrict__ L1,
    __nv_bfloat16* __restrict__ L2,
    int M, int N, int K)
{
    extern __shared__ char smc[];
    const int z = blockIdx.z;
    const float* A    = (z == 0) ? A0 : (z == 1) ? A1 : A2;
    const float* Bw   = (z == 0) ? W0 : (z == 1) ? W1 : W2;
    const float* bias = (z == 0) ? bs0 : (z == 1) ? bs1 : bs2;
    __nv_bfloat16* Ch = (z == 0) ? H0 : (z == 1) ? H1 : H2;
    __nv_bfloat16* Cl = (z == 0) ? L0 : (z == 1) ? L1 : L2;
    const float scale = (z == 0) ? 0.125f : 1.0f;

    const int m0 = blockIdx.y * 128;
    const int n0 = blockIdx.x * 128;
    float acc[4][4][4];
    gemm_mainloop(A, Bw, K, smc, m0, n0, acc);

    const int wid = threadIdx.x >> 5, lane = threadIdx.x & 31;
    const int g = lane >> 2, t = lane & 3;
    const int warp_m = wid & 1, warp_n = wid >> 1;

#pragma unroll
    for (int mi = 0; mi < 4; mi++) {
        const int row0 = m0 + warp_m * 64 + mi * 16 + g;
#pragma unroll
        for (int ni = 0; ni < 4; ni++) {
            const int col = n0 + warp_n * 32 + ni * 8 + t * 2;
            float2 bi = *(const float2*)&bias[col];
            float c0 = (acc[mi][ni][0] + bi.x) * scale;
            float c1 = (acc[mi][ni][1] + bi.y) * scale;
            float c2 = (acc[mi][ni][2] + bi.x) * scale;
            float c3 = (acc[mi][ni][3] + bi.y) * scale;
            __nv_bfloat162 h01 = __floats2bfloat162_rn(c0, c1);
            __nv_bfloat162 h23 = __floats2bfloat162_rn(c2, c3);
            float2 f01 = __bfloat1622float2(h01);
            float2 f23 = __bfloat1622float2(h23);
            __nv_bfloat162 l01 = __floats2bfloat162_rn(c0 - f01.x, c1 - f01.y);
            __nv_bfloat162 l23 = __floats2bfloat162_rn(c2 - f23.x, c3 - f23.y);
            *(__nv_bfloat162*)&Ch[(size_t)row0 * N + col] = h01;
            *(__nv_bfloat162*)&Ch[(size_t)(row0 + 8) * N + col] = h23;
            *(__nv_bfloat162*)&Cl[(size_t)row0 * N + col] = l01;
            *(__nv_bfloat162*)&Cl[(size_t)(row0 + 8) * N + col] = l23;
        }
    }
}

// ---- Output projection: fp32 epilogue ----
__global__ __launch_bounds__(256, 2) void gemm_f32(
    const float* __restrict__ A, const float* __restrict__ Bw,
    const float* __restrict__ bias, float* __restrict__ C,
    int M, int N, int K)
{
    extern __shared__ char smc[];
    const int m0 = blockIdx.y * 128;
    const int n0 = blockIdx.x * 128;
    float acc[4][4][4];
    gemm_mainloop(A, Bw, K, smc, m0, n0, acc);

    const int wid = threadIdx.x >> 5, lane = threadIdx.x & 31;
    const int g = lane >> 2, t = lane & 3;
    const int warp_m = wid & 1, warp_n = wid >> 1;

#pragma unroll
    for (int mi = 0; mi < 4; mi++) {
        const int row0 = m0 + warp_m * 64 + mi * 16 + g;
#pragma unroll
        for (int ni = 0; ni < 4; ni++) {
            const int col = n0 + warp_n * 32 + ni * 8 + t * 2;
            float2 bi = *(const float2*)&bias[col];
            float2 o0, o1;
            o0.x = acc[mi][ni][0] + bi.x;
            o0.y = acc[mi][ni][1] + bi.y;
            o1.x = acc[mi][ni][2] + bi.x;
            o1.y = acc[mi][ni][3] + bi.y;
            *(float2*)&C[(size_t)row0 * N + col] = o0;
            *(float2*)&C[(size_t)(row0 + 8) * N + col] = o1;
        }
    }
}

// ===========================================================================
// Tensor-core flash attention (R14 verbatim except mask -> bitmask LDG.64x2)
// ===========================================================================
#define FSTB 144
#define FQ_H 0
#define FQ_L (128 * FSTB)              // 18432
#define FB_KH 0
#define FB_KL (64 * FSTB)              // 9216
#define FB_VH (2 * 64 * FSTB)          // 18432
#define FB_VL (3 * 64 * FSTB)          // 27648
#define FBUF_SZ (4 * 64 * FSTB)        // 36864
#define FBUF0 (2 * 128 * FSTB)         // 36864
#define FLASH_SMEM (FBUF0 + 2 * FBUF_SZ)   // 110592

__global__ __launch_bounds__(256, 2) void flash_tc(
    const __nv_bfloat16* __restrict__ QH, const __nv_bfloat16* __restrict__ QL,
    const __nv_bfloat16* __restrict__ KH, const __nv_bfloat16* __restrict__ KL,
    const __nv_bfloat16* __restrict__ VH, const __nv_bfloat16* __restrict__ VL,
    float* __restrict__ ctx)
{
    extern __shared__ char smf[];
    const uint32_t sb = smem_u32(smf);
    const int tid = threadIdx.x;
    const int wid = tid >> 5, lane = tid & 31;
    const int g = lane >> 2, t = lane & 3;
    const int b = blockIdx.z, h = blockIdx.y;
    const int q0 = blockIdx.x * 128;

    const size_t bS = (size_t)b * S_;

    const int l7 = lane & 7;
    const int lh = (lane >> 3) & 1;
    const int lq = lane >> 4;
    const uint32_t qBase = sb +
        (uint32_t)(wid * 16 + l7 + lh * 8) * FSTB + (uint32_t)lq * 16;
    const uint32_t kRel = (uint32_t)l7 * FSTB + (uint32_t)lh * 16;
    const uint32_t vRel = (uint32_t)(l7 + lh * 8) * FSTB;

    const int kr = tid >> 2;
    const uint32_t cc = (uint32_t)(tid & 3) * 32;
    const size_t kvElemBase = (bS + kr) * D_ + h * DK_;

    // ---- Prologue: cp.async Q (whole) + K/V tile 0 ----
    {
        const int qr = tid >> 1;
        const uint32_t qcc = (uint32_t)(tid & 1) * 64;
        const char* srcQH = (const char*)(QH + (bS + q0 + qr) * D_ + h * DK_) + qcc;
        const char* srcQL = (const char*)(QL + (bS + q0 + qr) * D_ + h * DK_) + qcc;
        const uint32_t dq = sb + (uint32_t)qr * FSTB + qcc;
#pragma unroll
        for (int j = 0; j < 4; j++) {
            CP16(dq + FQ_H + j * 16, srcQH + j * 16);
            CP16(dq + FQ_L + j * 16, srcQL + j * 16);
        }
        const uint32_t d0 = sb + FBUF0 + (uint32_t)kr * FSTB + cc;
        const char* sKH = (const char*)(KH + kvElemBase) + cc;
        const char* sKL = (const char*)(KL + kvElemBase) + cc;
        const char* sVH = (const char*)(VH + kvElemBase) + cc;
        const char* sVL = (const char*)(VL + kvElemBase) + cc;
        CP16(d0 + FB_KH, sKH);       CP16(d0 + FB_KH + 16, sKH + 16);
        CP16(d0 + FB_KL, sKL);       CP16(d0 + FB_KL + 16, sKL + 16);
        CP16(d0 + FB_VH, sVH);       CP16(d0 + FB_VH + 16, sVH + 16);
        CP16(d0 + FB_VL, sVL);       CP16(d0 + FB_VL + 16, sVL + 16);
        CP_COMMIT();
        CP_WAIT0();
    }
    __syncthreads();

    // ---- Hoist Q hi+lo fragments for the whole kernel ----
    uint32_t qh[4][4], ql[4][4];
#pragma unroll
    for (int ks = 0; ks < 4; ks++) {
        LDSM_X4(qh[ks], qBase + FQ_H + ks * 32);
        LDSM_X4(ql[ks], qBase + FQ_L + ks * 32);
    }

    float O[8][4];
#pragma unroll
    for (int ni = 0; ni < 8; ni++)
#pragma unroll
        for (int c = 0; c < 4; c++) O[ni][c] = 0.f;

    float m0r = -3.0e38f, m1r = -3.0e38f;
    float l0r = 0.f, l1r = 0.f;

    const int r0g = q0 + wid * 16 + g;
    const int r1g = r0g + 8;
    const size_t mb0 = (bS + r0g) * (size_t)(S_ / 32);
    const size_t mb1 = (bS + r1g) * (size_t)(S_ / 32);

    const int NT = S_ / 64;
    for (int it = 0; it < NT; it++) {
        const uint32_t bb = sb + FBUF0 + (uint32_t)(it & 1) * FBUF_SZ;
        const int kt = it * 64;

        // Mask bit words for this tile (issued early to hide latency)
        uint2 mw0 = *(const uint2*)&g_mb[mb0 + it * 2];
        uint2 mw1 = *(const uint2*)&g_mb[mb1 + it * 2];

        // ---- S = Qs @ K^T (3-term split) ----
        float s[8][4];
#pragma unroll
        for (int ni = 0; ni < 8; ni++)
#pragma unroll
            for (int c = 0; c < 4; c++) s[ni][c] = 0.f;

#pragma unroll
        for (int ks = 0; ks < 4; ks++) {
#pragma unroll
            for (int ni = 0; ni < 8; ni++) {
                uint32_t kh[2], kl[2];
                LDSM_X2(kh, bb + FB_KH + kRel + ni * (8 * FSTB) + ks * 32);
                LDSM_X2(kl, bb + FB_KL + kRel + ni * (8 * FSTB) + ks * 32);
                MMA16816(s[ni], qh[ks], kh);
                MMA16816(s[ni], qh[ks], kl);
                MMA16816(s[ni], ql[ks], kh);
            }
        }

        // ---- Mask from packed bits ----
#pragma unroll
        for (int ni = 0; ni < 8; ni++) {
            const int bit = (ni * 8 + t * 2) & 31;
            const uint32_t w0 = (ni < 4) ? mw0.x : mw0.y;
            const uint32_t w1 = (ni < 4) ? mw1.x : mw1.y;
            if (!((w0 >> bit) & 1u))       s[ni][0] = NEGV;
            if (!((w0 >> (bit + 1)) & 1u)) s[ni][1] = NEGV;
            if (!((w1 >> bit) & 1u))       s[ni][2] = NEGV;
            if (!((w1 >> (bit + 1)) & 1u)) s[ni][3] = NEGV;
        }

        // ---- Online softmax (within t-quad) ----
        float mx0 = s[0][0], mx1 = s[0][2];
#pragma unroll
        for (int ni = 0; ni < 8; ni++) {
            mx0 = fmaxf(mx0, fmaxf(s[ni][0], s[ni][1]));
            mx1 = fmaxf(mx1, fmaxf(s[ni][2], s[ni][3]));
        }
        mx0 = fmaxf(mx0, __shfl_xor_sync(0xffffffffu, mx0, 1));
        mx0 = fmaxf(mx0, __shfl_xor_sync(0xffffffffu, mx0, 2));
        mx1 = fmaxf(mx1, __shfl_xor_sync(0xffffffffu, mx1, 1));
        mx1 = fmaxf(mx1, __shfl_xor_sync(0xffffffffu, mx1, 2));

        const float mn0 = fmaxf(m0r, mx0);
        const float mn1 = fmaxf(m1r, mx1);
        const float a0 = __expf(m0r - mn0);
        const float a1 = __expf(m1r - mn1);
        m0r = mn0; m1r = mn1;

        float sum0 = 0.f, sum1 = 0.f;
#pragma unroll
        for (int ni = 0; ni < 8; ni++) {
            s[ni][0] = __expf(s[ni][0] - mn0);
            s[ni][1] = __expf(s[ni][1] - mn0);
            s[ni][2] = __expf(s[ni][2] - mn1);
            s[ni][3] = __expf(s[ni][3] - mn1);
            sum0 += s[ni][0] + s[ni][1];
            sum1 += s[ni][2] + s[ni][3];
        }
        sum0 += __shfl_xor_sync(0xffffffffu, sum0, 1);
        sum0 += __shfl_xor_sync(0xffffffffu, sum0, 2);
        sum1 += __shfl_xor_sync(0xffffffffu, sum1, 1);
        sum1 += __shfl_xor_sync(0xffffffffu, sum1, 2);
        l0r = l0r * a0 + sum0;
        l1r = l1r * a1 + sum1;

#pragma unroll
        for (int ni = 0; ni < 8; ni++) {
            O[ni][0] *= a0; O[ni][1] *= a0;
            O[ni][2] *= a1; O[ni][3] *= a1;
        }

        // ---- cp.async next tile ----
        if (it + 1 < NT) {
            const size_t nb = kvElemBase + (size_t)(kt + 64) * D_;
            const uint32_t dn = sb + FBUF0 + (uint32_t)((it + 1) & 1) * FBUF_SZ
                              + (uint32_t)kr * FSTB + cc;
            const char* sKH = (const char*)(KH + nb) + cc;
            const char* sKL = (const char*)(KL + nb) + cc;
            const char* sVH = (const char*)(VH + nb) + cc;
            const char* sVL = (const char*)(VL + nb) + cc;
            CP16(dn + FB_KH, sKH);    CP16(dn + FB_KH + 16, sKH + 16);
            CP16(dn + FB_KL, sKL);    CP16(dn + FB_KL + 16, sKL + 16);
            CP16(dn + FB_VH, sVH);    CP16(dn + FB_VH + 16, sVH + 16);
            CP16(dn + FB_VL, sVL);    CP16(dn + FB_VL + 16, sVL + 16);
            CP_COMMIT();
        }

        // ---- PV: O += P @ V (P from regs; V frags via ldmatrix.trans) ----
#pragma unroll
        for (int ksp = 0; ksp < 4; ksp++) {
            uint32_t pah[4], pal[4];
#pragma unroll
            for (int hf = 0; hf < 2; hf++) {
                const float* p = s[2 * ksp + hf];
                __nv_bfloat162 h01 = __floats2bfloat162_rn(p[0], p[1]);
                __nv_bfloat162 h23 = __floats2bfloat162_rn(p[2], p[3]);
                float2 f01 = __bfloat1622float2(h01);
                float2 f23 = __bfloat1622float2(h23);
                __nv_bfloat162 l01 =
                    __floats2bfloat162_rn(p[0] - f01.x, p[1] - f01.y);
                __nv_bfloat162 l23 =
                    __floats2bfloat162_rn(p[2] - f23.x, p[3] - f23.y);
                pah[hf * 2 + 0] = *(const uint32_t*)&h01;
                pah[hf * 2 + 1] = *(const uint32_t*)&h23;
                pal[hf * 2 + 0] = *(const uint32_t*)&l01;
                pal[hf * 2 + 1] = *(const uint32_t*)&l23;
            }
#pragma unroll
            for (int ni = 0; ni < 8; ni++) {
                uint32_t vh[2], vl[2];
                LDSM_X2T(vh, bb + FB_VH + vRel + ksp * (16 * FSTB) + ni * 16);
                LDSM_X2T(vl, bb + FB_VL + vRel + ksp * (16 * FSTB) + ni * 16);
                MMA16816(O[ni], pah, vh);
                MMA16816(O[ni], pah, vl);
                MMA16816(O[ni], pal, vh);
            }
        }

        CP_WAIT0();
        __syncthreads();
    }

    // ---- Final normalize + store ----
    const float ri0 = 1.f / l0r;
    const float ri1 = 1.f / l1r;
    float* C0 = ctx + (bS + r0g) * D_ + h * DK_;
    float* C1 = ctx + (bS + r1g) * D_ + h * DK_;
#pragma unroll
    for (int ni = 0; ni < 8; ni++) {
        const int c = ni * 8 + t * 2;
        float2 o0, o1;
        o0.x = O[ni][0] * ri0; o0.y = O[ni][1] * ri0;
        o1.x = O[ni][2] * ri1; o1.y = O[ni][3] * ri1;
        *(float2*)(C0 + c) = o0;
        *(float2*)(C1 + c) = o1;
    }
}

// ---------------------------------------------------------------------------
// Launch
// ---------------------------------------------------------------------------
extern "C" void kernel_launch(void* const* d_in, const int* in_sizes, int n_in,
                              void* d_out, int out_size)
{
    const float* query = (const float*)d_in[0];
    const float* key   = (const float*)d_in[1];
    const float* value = (const float*)d_in[2];
    const int*   mask  = (const int*)d_in[3];
    const float* w_q = (const float*)d_in[4];
    const float* b_q = (const float*)d_in[5];
    const float* w_k = (const float*)d_in[6];
    const float* b_k = (const float*)d_in[7];
    const float* w_v = (const float*)d_in[8];
    const float* b_v = (const float*)d_in[9];
    const float* w_o = (const float*)d_in[10];
    const float* b_o = (const float*)d_in[11];

    __nv_bfloat16 *qh, *ql, *kh, *kl, *vh, *vl;
    float *gc;
    cudaGetSymbolAddress((void**)&qh, g_qh);
    cudaGetSymbolAddress((void**)&ql, g_ql);
    cudaGetSymbolAddress((void**)&kh, g_kh);
    cudaGetSymbolAddress((void**)&kl, g_kl);
    cudaGetSymbolAddress((void**)&vh, g_vh);
    cudaGetSymbolAddress((void**)&vl, g_vl);
    cudaGetSymbolAddress((void**)&gc, g_ctx);

    cudaFuncSetAttribute(gemm_split,
                         cudaFuncAttributeMaxDynamicSharedMemorySize,
                         GEMM_SMEM);
    cudaFuncSetAttribute(gemm_f32,
                         cudaFuncAttributeMaxDynamicSharedMemorySize,
                         GEMM_SMEM);
    cudaFuncSetAttribute(flash_tc,
                         cudaFuncAttributeMaxDynamicSharedMemorySize,
                         FLASH_SMEM);

    const int M = B_ * S_;                        // 4096

    // Mask bitpack (needed by flash, 3rd kernel)
    maskpack<<<(B_ * S_ * S_) / 256, 256>>>(mask);

    // Fused QKV projections: grid.z selects (A, W, bias, out) tuple.
    dim3 gqkv(D_ / 128, M / 128, 3);              // 768 CTAs
    gemm_split<<<gqkv, 256, GEMM_SMEM>>>(
        query, key, value,
        w_q, w_k, w_v,
        b_q, b_k, b_v,
        qh, kh, vh,
        ql, kl, vl,
        M, D_, D_);

    dim3 gflash(S_ / 128, H_, B_);                // 512 CTAs
    flash_tc<<<gflash, 256, FLASH_SMEM>>>(qh, ql, kh, kl, vh, vl, gc);

    dim3 gproj(D_ / 128, M / 128);
    gemm_f32<<<gproj, 256, GEMM_SMEM>>>(gc, w_o, b_o, (float*)d_out, M, D_, D_);
}